// round 3
// baseline (speedup 1.0000x reference)
#include <cuda_runtime.h>
#include <cstdint>

#define DIM 128
#define MAXN 50176          // slack over 50000, multiple of 128
#define BM 128
#define BK 32
#define AP 132              // padded smem row length (words), multiple of 4

__device__ float g_hpre[MAXN * DIM];   // x + agg  (GIN pre-MLP)
__device__ float g_h1[MAXN * DIM];     // after Linear1 (+b1), pre-BN
__device__ float g_stats[2 * DIM];     // [0:128) colsum, [128:256) colsumsq
__device__ float g_scale[DIM];         // gamma * rstd
__device__ float g_shift[DIM];         // beta - mu * gamma * rstd

// ---------------------------------------------------------------------------
// K0: h_pre = x ; zero stats accumulators
// ---------------------------------------------------------------------------
__global__ void init_kernel(const float* __restrict__ x, int n4) {
    int gid = blockIdx.x * blockDim.x + threadIdx.x;
    if (gid < 2 * DIM) g_stats[gid] = 0.0f;
    if (gid < n4) ((float4*)g_hpre)[gid] = ((const float4*)x)[gid];
}

// ---------------------------------------------------------------------------
// K1: scatter-add  h_pre[dst] += x[src]   (warp per edge)
// Each lane handles 4 contiguous floats -> one LDG.128 + one red.global.v4.f32
// NOTE: edge_index is int32 (JAX x64 disabled -> int64 request yields int32).
// ---------------------------------------------------------------------------
__global__ void scatter_kernel(const float* __restrict__ x,
                               const int* __restrict__ ei,
                               int n_edges) {
    int g = blockIdx.x * blockDim.x + threadIdx.x;
    int e = g >> 5;
    int lane = g & 31;
    if (e >= n_edges) return;
    int src = ei[e];
    int dst = ei[n_edges + e];
    const float4* xs = (const float4*)(x + (size_t)src * DIM) + lane;
    float4* hd = (float4*)(g_hpre + (size_t)dst * DIM) + lane;
    float4 v = __ldg(xs);
    asm volatile("red.global.add.v4.f32 [%0], {%1, %2, %3, %4};"
                 :: "l"(hd), "f"(v.x), "f"(v.y), "f"(v.z), "f"(v.w)
                 : "memory");
}

// ---------------------------------------------------------------------------
// GEMM kernels: BM=128 rows/block, full N=128, BK=32 chunks, 256 thr, 8x8 tile
// PHASE 1: h1 = h_pre @ W1^T + b1 ; accumulate column sum/sumsq for BN
// PHASE 2: out = lrelu_0.2( lrelu_0.01(bn(h1)) @ W2^T + b2 + x @ Wres^T )
//          implemented as a single K=256 GEMM over [bn'd h1 | x] and [W2|Wres]
// ---------------------------------------------------------------------------
template <int PHASE>
__global__ __launch_bounds__(256, 2)
void gemm_kernel(const float* __restrict__ Ax,     // phase2: x          (phase1: unused)
                 const float* __restrict__ W0,     // W1 / W2
                 const float* __restrict__ W1p,    // -  / Wres
                 const float* __restrict__ bias,   // b1 / b2
                 float* __restrict__ outp,         // phase2: d_out      (phase1: unused)
                 int M) {
    __shared__ float Ast[BK * AP];                 // k-major A tile  Ast[k][m]
    __shared__ float Ws [BK * AP];                 // k-major W tile  Ws[k][n]
    __shared__ float ssc[DIM];
    __shared__ float ssh[DIM];

    const int tid = threadIdx.x;
    const int tr = tid >> 4;           // 0..15
    const int tc = tid & 15;           // 0..15
    const int row0 = tr * 8;
    const int col0 = tc * 8;
    const int rowBase = blockIdx.x * BM;

    if (PHASE == 2) {
        if (tid < DIM) { ssc[tid] = g_scale[tid]; ssh[tid] = g_shift[tid]; }
    }
    __syncthreads();

    float acc[64];
#pragma unroll
    for (int i = 0; i < 64; i++) acc[i] = 0.0f;

    const int NCHUNK = (PHASE == 1) ? 4 : 8;

#pragma unroll 1
    for (int kc = 0; kc < NCHUNK; kc++) {
        const int kbase = kc * BK;

        // ---- load A tile (transposed into smem), apply BN+leaky in phase2 ----
#pragma unroll
        for (int t = 0; t < 4; t++) {
            int idx = tid + t * 256;
            int m = idx >> 3;
            int f4 = (idx & 7) * 4;
            int gr = rowBase + m;
            float4 v = make_float4(0.f, 0.f, 0.f, 0.f);
            if (PHASE == 1) {
                if (gr < M) v = *(const float4*)(g_hpre + (size_t)gr * DIM + kbase + f4);
            } else {
                if (kbase < DIM) {
                    if (gr < M) {
                        v = *(const float4*)(g_h1 + (size_t)gr * DIM + kbase + f4);
                        int kk = kbase + f4;
                        v.x = v.x * ssc[kk + 0] + ssh[kk + 0];
                        v.y = v.y * ssc[kk + 1] + ssh[kk + 1];
                        v.z = v.z * ssc[kk + 2] + ssh[kk + 2];
                        v.w = v.w * ssc[kk + 3] + ssh[kk + 3];
                        v.x = v.x > 0.f ? v.x : 0.01f * v.x;
                        v.y = v.y > 0.f ? v.y : 0.01f * v.y;
                        v.z = v.z > 0.f ? v.z : 0.01f * v.z;
                        v.w = v.w > 0.f ? v.w : 0.01f * v.w;
                    }
                } else {
                    if (gr < M) v = *(const float4*)(Ax + (size_t)gr * DIM + (kbase - DIM) + f4);
                }
            }
            Ast[(f4 + 0) * AP + m] = v.x;
            Ast[(f4 + 1) * AP + m] = v.y;
            Ast[(f4 + 2) * AP + m] = v.z;
            Ast[(f4 + 3) * AP + m] = v.w;
        }

        // ---- load W tile (transposed into smem) ----
#pragma unroll
        for (int t = 0; t < 4; t++) {
            int idx = tid + t * 256;
            int n = idx >> 3;
            int f4 = (idx & 7) * 4;
            const float* Wsrc;
            int kk;
            if (PHASE == 1) { Wsrc = W0; kk = kbase; }
            else if (kbase < DIM) { Wsrc = W0; kk = kbase; }
            else { Wsrc = W1p; kk = kbase - DIM; }
            float4 v = *(const float4*)(Wsrc + (size_t)n * DIM + kk + f4);
            Ws[(f4 + 0) * AP + n] = v.x;
            Ws[(f4 + 1) * AP + n] = v.y;
            Ws[(f4 + 2) * AP + n] = v.z;
            Ws[(f4 + 3) * AP + n] = v.w;
        }
        __syncthreads();

        // ---- 8x8 register-tile FFMA mainloop ----
#pragma unroll
        for (int k = 0; k < BK; k++) {
            float a[8], b[8];
            float4 t0 = *(const float4*)(Ast + k * AP + row0);
            float4 t1 = *(const float4*)(Ast + k * AP + row0 + 4);
            a[0] = t0.x; a[1] = t0.y; a[2] = t0.z; a[3] = t0.w;
            a[4] = t1.x; a[5] = t1.y; a[6] = t1.z; a[7] = t1.w;
            float4 u0 = *(const float4*)(Ws + k * AP + col0);
            float4 u1 = *(const float4*)(Ws + k * AP + col0 + 4);
            b[0] = u0.x; b[1] = u0.y; b[2] = u0.z; b[3] = u0.w;
            b[4] = u1.x; b[5] = u1.y; b[6] = u1.z; b[7] = u1.w;
#pragma unroll
            for (int i = 0; i < 8; i++)
#pragma unroll
                for (int j = 0; j < 8; j++)
                    acc[i * 8 + j] = fmaf(a[i], b[j], acc[i * 8 + j]);
        }
        __syncthreads();
    }

    // ---- epilogue ----
    float bb[8];
#pragma unroll
    for (int j = 0; j < 8; j++) bb[j] = __ldg(bias + col0 + j);

    if (PHASE == 1) {
        float ssum[8], ssq[8];
#pragma unroll
        for (int j = 0; j < 8; j++) { ssum[j] = 0.f; ssq[j] = 0.f; }
#pragma unroll
        for (int i = 0; i < 8; i++) {
            int gr = rowBase + row0 + i;
            if (gr < M) {
                float v[8];
#pragma unroll
                for (int j = 0; j < 8; j++) {
                    v[j] = acc[i * 8 + j] + bb[j];
                    ssum[j] += v[j];
                    ssq[j] += v[j] * v[j];
                }
                float4 o0 = make_float4(v[0], v[1], v[2], v[3]);
                float4 o1 = make_float4(v[4], v[5], v[6], v[7]);
                *(float4*)(g_h1 + (size_t)gr * DIM + col0) = o0;
                *(float4*)(g_h1 + (size_t)gr * DIM + col0 + 4) = o1;
            }
        }
        // block-level column reduction into g_stats
        float* red = Ast;   // 4096 floats needed, Ast holds 4224
#pragma unroll
        for (int j = 0; j < 8; j++) {
            red[tr * DIM + col0 + j] = ssum[j];
            red[2048 + tr * DIM + col0 + j] = ssq[j];
        }
        __syncthreads();
        if (tid < DIM) {
            float s = 0.f, s2 = 0.f;
#pragma unroll
            for (int r = 0; r < 16; r++) {
                s  += red[r * DIM + tid];
                s2 += red[2048 + r * DIM + tid];
            }
            atomicAdd(&g_stats[tid], s);
            atomicAdd(&g_stats[DIM + tid], s2);
        }
    } else {
#pragma unroll
        for (int i = 0; i < 8; i++) {
            int gr = rowBase + row0 + i;
            if (gr < M) {
                float v[8];
#pragma unroll
                for (int j = 0; j < 8; j++) {
                    float t = acc[i * 8 + j] + bb[j];
                    v[j] = t > 0.f ? t : 0.2f * t;
                }
                float4 o0 = make_float4(v[0], v[1], v[2], v[3]);
                float4 o1 = make_float4(v[4], v[5], v[6], v[7]);
                *(float4*)(outp + (size_t)gr * DIM + col0) = o0;
                *(float4*)(outp + (size_t)gr * DIM + col0 + 4) = o1;
            }
        }
    }
}

// ---------------------------------------------------------------------------
// K3: finalize BN affine params
// ---------------------------------------------------------------------------
__global__ void bn_kernel(const float* __restrict__ gamma,
                          const float* __restrict__ beta, float invN) {
    int c = threadIdx.x;
    if (c < DIM) {
        float mu  = g_stats[c] * invN;
        float var = g_stats[DIM + c] * invN - mu * mu;
        float rstd = rsqrtf(var + 1e-5f);
        float g = gamma[c] * rstd;
        g_scale[c] = g;
        g_shift[c] = beta[c] - mu * g;
    }
}

// ---------------------------------------------------------------------------
extern "C" void kernel_launch(void* const* d_in, const int* in_sizes, int n_in,
                              void* d_out, int out_size) {
    const float* x        = (const float*)d_in[0];
    const int* ei         = (const int*)d_in[1];
    const float* W1       = (const float*)d_in[2];
    const float* b1       = (const float*)d_in[3];
    const float* gamma    = (const float*)d_in[4];
    const float* beta     = (const float*)d_in[5];
    const float* W2       = (const float*)d_in[6];
    const float* b2       = (const float*)d_in[7];
    const float* Wres     = (const float*)d_in[8];
    float* out            = (float*)d_out;

    int M = in_sizes[0] / DIM;       // 50000
    int E = in_sizes[1] / 2;         // 600000
    int n4 = M * (DIM / 4);

    init_kernel<<<(n4 + 255) / 256, 256>>>(x, n4);
    {
        long long work = (long long)E * 32;
        int blocks = (int)((work + 255) / 256);
        scatter_kernel<<<blocks, 256>>>(x, ei, E);
    }
    int gb = (M + BM - 1) / BM;
    gemm_kernel<1><<<gb, 256>>>(nullptr, W1, nullptr, b1, nullptr, M);
    bn_kernel<<<1, DIM>>>(gamma, beta, 1.0f / (float)M);
    gemm_kernel<2><<<gb, 256>>>(x, W2, Wres, b2, out, M);
}

// round 5
// speedup vs baseline: 1.5005x; 1.5005x over previous
#include <cuda_runtime.h>
#include <cstdint>

#define DIM 128
#define MAXN 50176
#define BM 128
#define BK 32
#define AP 36               // padded smem row pitch in words (bank-conflict-free: 36g+tg)

__device__ float g_hpre[MAXN * DIM];   // x + agg
__device__ float g_h1[MAXN * DIM];     // Linear1 output, pre-BN
__device__ float g_stats[2 * DIM];     // colsum | colsumsq
__device__ float g_scale[DIM];
__device__ float g_shift[DIM];

// ---------------------------------------------------------------------------
__global__ void init_kernel(const float* __restrict__ x, int n4) {
    int gid = blockIdx.x * blockDim.x + threadIdx.x;
    if (gid < 2 * DIM) g_stats[gid] = 0.0f;
    if (gid < n4) ((float4*)g_hpre)[gid] = ((const float4*)x)[gid];
}

// ---------------------------------------------------------------------------
// scatter-add: warp per edge, lane = 4 floats -> LDG.128 + red.global.v4.f32
__global__ void scatter_kernel(const float* __restrict__ x,
                               const int* __restrict__ ei,
                               int n_edges) {
    int g = blockIdx.x * blockDim.x + threadIdx.x;
    int e = g >> 5;
    int lane = g & 31;
    if (e >= n_edges) return;
    int src = ei[e];
    int dst = ei[n_edges + e];
    const float4* xs = (const float4*)(x + (size_t)src * DIM) + lane;
    float4* hd = (float4*)(g_hpre + (size_t)dst * DIM) + lane;
    float4 v = __ldg(xs);
    asm volatile("red.global.add.v4.f32 [%0], {%1, %2, %3, %4};"
                 :: "l"(hd), "f"(v.x), "f"(v.y), "f"(v.z), "f"(v.w)
                 : "memory");
}

// ---------------------------------------------------------------------------
__device__ __forceinline__ unsigned f2tf(float f) {
    unsigned r;
    asm("cvt.rna.tf32.f32 %0, %1;" : "=r"(r) : "f"(f));
    return r;
}

__device__ __forceinline__ void mma_tf32(float* c, const unsigned* a, const unsigned* b) {
    asm volatile(
        "mma.sync.aligned.m16n8k8.row.col.f32.tf32.tf32.f32 "
        "{%0,%1,%2,%3}, {%4,%5,%6,%7}, {%8,%9}, {%0,%1,%2,%3};"
        : "+f"(c[0]), "+f"(c[1]), "+f"(c[2]), "+f"(c[3])
        : "r"(a[0]), "r"(a[1]), "r"(a[2]), "r"(a[3]), "r"(b[0]), "r"(b[1]));
}

// ---------------------------------------------------------------------------
// tf32 tensor-core GEMM, 128x128 block tile, 8 warps (4m x 2n), 32x64 warp tile
// PHASE 1: h1 = h_pre @ W1^T + b1 ; BN column sum/sumsq
// PHASE 2: out = lrelu_.2( lrelu_.01(bn(h1)) @ W2^T + x @ Wres^T + b2 ), K=256
// ---------------------------------------------------------------------------
template <int PHASE>
__global__ __launch_bounds__(256, 2)
void gemm_kernel(const float* __restrict__ Ax,
                 const float* __restrict__ W0,
                 const float* __restrict__ W1p,
                 const float* __restrict__ bias,
                 float* __restrict__ outp,
                 int M) {
    __shared__ unsigned As[BM * AP];    // A tile, row-major [m][k], tf32 bits
    __shared__ unsigned Ws[DIM * AP];   // W tile, row-major [n][k], tf32 bits
    __shared__ float s_sum[DIM];
    __shared__ float s_sq[DIM];
    __shared__ float ssc[DIM];
    __shared__ float ssh[DIM];

    const int tid  = threadIdx.x;
    const int wid  = tid >> 5;
    const int lane = tid & 31;
    const int g    = lane >> 2;        // 0..7
    const int tg   = lane & 3;         // 0..3
    const int wm   = wid & 3;          // 0..3  (m tile of 32)
    const int wn   = wid >> 2;         // 0..1  (n tile of 64)
    const int rowBase = blockIdx.x * BM;

    if (PHASE == 1) {
        if (tid < DIM) { s_sum[tid] = 0.f; s_sq[tid] = 0.f; }
    } else {
        if (tid < DIM) { ssc[tid] = g_scale[tid]; ssh[tid] = g_shift[tid]; }
    }
    __syncthreads();

    float acc[2][8][4];
#pragma unroll
    for (int i = 0; i < 2; i++)
#pragma unroll
        for (int j = 0; j < 8; j++)
#pragma unroll
            for (int r = 0; r < 4; r++) acc[i][j][r] = 0.f;

    const int NCHUNK = (PHASE == 1) ? 4 : 8;

#pragma unroll 1
    for (int kc = 0; kc < NCHUNK; kc++) {
        const int kbase = kc * BK;

        // ---- A tile: 4 float4 per thread, cvt->tf32, row-major ----
#pragma unroll
        for (int t = 0; t < 4; t++) {
            int idx = tid + t * 256;
            int m = idx >> 3;
            int f4 = (idx & 7) * 4;
            int gr = rowBase + m;
            float4 v = make_float4(0.f, 0.f, 0.f, 0.f);
            if (PHASE == 1) {
                if (gr < M) v = *(const float4*)(g_hpre + (size_t)gr * DIM + kbase + f4);
            } else {
                if (kbase < DIM) {
                    if (gr < M) {
                        v = *(const float4*)(g_h1 + (size_t)gr * DIM + kbase + f4);
                        int kk = kbase + f4;
                        v.x = v.x * ssc[kk + 0] + ssh[kk + 0];
                        v.y = v.y * ssc[kk + 1] + ssh[kk + 1];
                        v.z = v.z * ssc[kk + 2] + ssh[kk + 2];
                        v.w = v.w * ssc[kk + 3] + ssh[kk + 3];
                        v.x = v.x > 0.f ? v.x : 0.01f * v.x;
                        v.y = v.y > 0.f ? v.y : 0.01f * v.y;
                        v.z = v.z > 0.f ? v.z : 0.01f * v.z;
                        v.w = v.w > 0.f ? v.w : 0.01f * v.w;
                    }
                } else {
                    if (gr < M) v = *(const float4*)(Ax + (size_t)gr * DIM + (kbase - DIM) + f4);
                }
            }
            unsigned* dstp = As + m * AP + f4;
            dstp[0] = f2tf(v.x); dstp[1] = f2tf(v.y);
            dstp[2] = f2tf(v.z); dstp[3] = f2tf(v.w);
        }

        // ---- W tile: row-major [n][k] (same as gmem layout) ----
#pragma unroll
        for (int t = 0; t < 4; t++) {
            int idx = tid + t * 256;
            int n = idx >> 3;
            int f4 = (idx & 7) * 4;
            const float* Wsrc;
            int kk;
            if (PHASE == 1) { Wsrc = W0; kk = kbase; }
            else if (kbase < DIM) { Wsrc = W0; kk = kbase; }
            else { Wsrc = W1p; kk = kbase - DIM; }
            float4 v = *(const float4*)(Wsrc + (size_t)n * DIM + kk + f4);
            unsigned* dstp = Ws + n * AP + f4;
            dstp[0] = f2tf(v.x); dstp[1] = f2tf(v.y);
            dstp[2] = f2tf(v.z); dstp[3] = f2tf(v.w);
        }
        __syncthreads();

        // ---- 4 k8-steps of m16n8k8 MMAs ----
#pragma unroll
        for (int k8 = 0; k8 < 4; k8++) {
            const int kof = k8 * 8;
            unsigned afrag[2][4];
#pragma unroll
            for (int mt = 0; mt < 2; mt++) {
                int r0 = wm * 32 + mt * 16 + g;
                afrag[mt][0] = As[(r0    ) * AP + kof + tg];
                afrag[mt][1] = As[(r0 + 8) * AP + kof + tg];
                afrag[mt][2] = As[(r0    ) * AP + kof + tg + 4];
                afrag[mt][3] = As[(r0 + 8) * AP + kof + tg + 4];
            }
            unsigned bfrag[8][2];
#pragma unroll
            for (int nt = 0; nt < 8; nt++) {
                int n0 = wn * 64 + nt * 8 + g;
                bfrag[nt][0] = Ws[n0 * AP + kof + tg];
                bfrag[nt][1] = Ws[n0 * AP + kof + tg + 4];
            }
#pragma unroll
            for (int mt = 0; mt < 2; mt++)
#pragma unroll
                for (int nt = 0; nt < 8; nt++)
                    mma_tf32(acc[mt][nt], afrag[mt], bfrag[nt]);
        }
        __syncthreads();
    }

    // ---- epilogue ----
    // thread owns rows {wm*32+mt*16+g, +8}, cols {wn*64+nt*8+tg*2, +1}
    if (PHASE == 1) {
        float tsum[8][2], tsq[8][2];
#pragma unroll
        for (int nt = 0; nt < 8; nt++)
            tsum[nt][0] = tsum[nt][1] = tsq[nt][0] = tsq[nt][1] = 0.f;

#pragma unroll
        for (int mt = 0; mt < 2; mt++) {
#pragma unroll
            for (int half = 0; half < 2; half++) {
                int gr = rowBase + wm * 32 + mt * 16 + g + half * 8;
                if (gr < M) {
#pragma unroll
                    for (int nt = 0; nt < 8; nt++) {
                        int c = wn * 64 + nt * 8 + tg * 2;
                        float v0 = acc[mt][nt][half * 2 + 0] + __ldg(bias + c);
                        float v1 = acc[mt][nt][half * 2 + 1] + __ldg(bias + c + 1);
                        tsum[nt][0] += v0;  tsum[nt][1] += v1;
                        tsq[nt][0] += v0 * v0;  tsq[nt][1] += v1 * v1;
                        *(float2*)(g_h1 + (size_t)gr * DIM + c) = make_float2(v0, v1);
                    }
                }
            }
        }
        // butterfly over g bits (lane bits 2..4): all lanes w/ same tg share cols
#pragma unroll
        for (int nt = 0; nt < 8; nt++) {
#pragma unroll
            for (int h = 0; h < 2; h++) {
#pragma unroll
                for (int ofs = 4; ofs < 32; ofs <<= 1) {
                    tsum[nt][h] += __shfl_xor_sync(0xffffffff, tsum[nt][h], ofs);
                    tsq[nt][h]  += __shfl_xor_sync(0xffffffff, tsq[nt][h], ofs);
                }
            }
        }
        if (g == 0) {
#pragma unroll
            for (int nt = 0; nt < 8; nt++) {
                int c = wn * 64 + nt * 8 + tg * 2;
                atomicAdd(&s_sum[c],     tsum[nt][0]);
                atomicAdd(&s_sum[c + 1], tsum[nt][1]);
                atomicAdd(&s_sq[c],      tsq[nt][0]);
                atomicAdd(&s_sq[c + 1],  tsq[nt][1]);
            }
        }
        __syncthreads();
        if (tid < DIM) {
            atomicAdd(&g_stats[tid],       s_sum[tid]);
            atomicAdd(&g_stats[DIM + tid], s_sq[tid]);
        }
    } else {
#pragma unroll
        for (int mt = 0; mt < 2; mt++) {
#pragma unroll
            for (int half = 0; half < 2; half++) {
                int gr = rowBase + wm * 32 + mt * 16 + g + half * 8;
                if (gr < M) {
#pragma unroll
                    for (int nt = 0; nt < 8; nt++) {
                        int c = wn * 64 + nt * 8 + tg * 2;
                        float v0 = acc[mt][nt][half * 2 + 0] + __ldg(bias + c);
                        float v1 = acc[mt][nt][half * 2 + 1] + __ldg(bias + c + 1);
                        v0 = v0 > 0.f ? v0 : 0.2f * v0;
                        v1 = v1 > 0.f ? v1 : 0.2f * v1;
                        *(float2*)(outp + (size_t)gr * DIM + c) = make_float2(v0, v1);
                    }
                }
            }
        }
    }
}

// ---------------------------------------------------------------------------
__global__ void bn_kernel(const float* __restrict__ gamma,
                          const float* __restrict__ beta, float invN) {
    int c = threadIdx.x;
    if (c < DIM) {
        float mu  = g_stats[c] * invN;
        float var = g_stats[DIM + c] * invN - mu * mu;
        float rstd = rsqrtf(var + 1e-5f);
        float s = gamma[c] * rstd;
        g_scale[c] = s;
        g_shift[c] = beta[c] - mu * s;
    }
}

// ---------------------------------------------------------------------------
extern "C" void kernel_launch(void* const* d_in, const int* in_sizes, int n_in,
                              void* d_out, int out_size) {
    const float* x     = (const float*)d_in[0];
    const int* ei      = (const int*)d_in[1];
    const float* W1    = (const float*)d_in[2];
    const float* b1    = (const float*)d_in[3];
    const float* gamma = (const float*)d_in[4];
    const float* beta  = (const float*)d_in[5];
    const float* W2    = (const float*)d_in[6];
    const float* b2    = (const float*)d_in[7];
    const float* Wres  = (const float*)d_in[8];
    float* out         = (float*)d_out;

    int M = in_sizes[0] / DIM;
    int E = in_sizes[1] / 2;
    int n4 = M * (DIM / 4);

    init_kernel<<<(n4 + 255) / 256, 256>>>(x, n4);
    {
        long long work = (long long)E * 32;
        int blocks = (int)((work + 255) / 256);
        scatter_kernel<<<blocks, 256>>>(x, ei, E);
    }
    int gb = (M + BM - 1) / BM;
    gemm_kernel<1><<<gb, 256>>>(nullptr, W1, nullptr, b1, nullptr, M);
    bn_kernel<<<1, DIM>>>(gamma, beta, 1.0f / (float)M);
    gemm_kernel<2><<<gb, 256>>>(x, W2, Wres, b2, out, M);
}